// round 1
// baseline (speedup 1.0000x reference)
#include <cuda_runtime.h>

#define N_MAX 100000
#define C 32

// Scratch (allocation-free): accumulators, transformed tables, hidden state, counts.
__device__ float4 g_A[N_MAX * 8];      // sum aggregation accumulator (temp edges)
__device__ float4 g_B[N_MAX * 8];      // sum accumulator (inter edges, divided by cnt later)
__device__ float4 g_ht[N_MAX * 8];     // x @ Wt + bt
__device__ float4 g_hi[N_MAX * 8];     // x @ Wi + bi
__device__ float4 g_h1[N_MAX * 8];     // block-1 output
__device__ float  g_cnt[N_MAX];        // in-degree for inter edges

// ---------------------------------------------------------------------------
__global__ void zero_kernel(int N) {
    int i = blockIdx.x * blockDim.x + threadIdx.x;
    int n4 = N * 8;
    if (i < n4) {
        g_A[i] = make_float4(0.f, 0.f, 0.f, 0.f);
    } else if (i < 2 * n4) {
        g_B[i - n4] = make_float4(0.f, 0.f, 0.f, 0.f);
    } else if (i < 2 * n4 + N) {
        g_cnt[i - 2 * n4] = 0.f;
    }
}

__global__ void count_kernel(const int* __restrict__ ei, int E) {
    int e = blockIdx.x * blockDim.x + threadIdx.x;
    if (e >= E) return;
    int d = ei[E + e];                 // row 1 = destination
    atomicAdd(&g_cnt[d], 1.0f);
}

// ---------------------------------------------------------------------------
// Transform: ht = in @ Wt + bt ; hi = in @ Wi + bi.
// One thread per (node, 4-wide output column group).
template <int K>
__global__ void transform_kernel(const float* __restrict__ in,
                                 const float* __restrict__ Wt,
                                 const float* __restrict__ bt,
                                 const float* __restrict__ Wi,
                                 const float* __restrict__ bi, int N) {
    __shared__ float sWt[K * 32];
    __shared__ float sWi[K * 32];
    __shared__ float sbt[32];
    __shared__ float sbi[32];
    for (int i = threadIdx.x; i < K * 32; i += blockDim.x) {
        sWt[i] = Wt[i];
        sWi[i] = Wi[i];
    }
    if (threadIdx.x < 32) {
        sbt[threadIdx.x] = bt[threadIdx.x];
        sbi[threadIdx.x] = bi[threadIdx.x];
    }
    __syncthreads();

    int t = blockIdx.x * blockDim.x + threadIdx.x;
    int n = t >> 3;
    int j = t & 7;
    int c = j * 4;
    if (n >= N) return;

    const float* src = (K == 32) ? (const float*)g_h1 : in;

    float4 at = make_float4(sbt[c], sbt[c + 1], sbt[c + 2], sbt[c + 3]);
    float4 ai = make_float4(sbi[c], sbi[c + 1], sbi[c + 2], sbi[c + 3]);
#pragma unroll
    for (int k = 0; k < K; k++) {
        float v = __ldg(&src[n * K + k]);
        at.x += v * sWt[k * 32 + c];
        at.y += v * sWt[k * 32 + c + 1];
        at.z += v * sWt[k * 32 + c + 2];
        at.w += v * sWt[k * 32 + c + 3];
        ai.x += v * sWi[k * 32 + c];
        ai.y += v * sWi[k * 32 + c + 1];
        ai.z += v * sWi[k * 32 + c + 2];
        ai.w += v * sWi[k * 32 + c + 3];
    }
    g_ht[n * 8 + j] = at;
    g_hi[n * 8 + j] = ai;
}

// ---------------------------------------------------------------------------
// Fused scatter for both edge types: A[dst] += ht[src] (temp), B[dst] += hi[src] (inter).
// 8 threads per edge, one float4 + one red.global.add.v4.f32 each.
__device__ __forceinline__ void red_add_v4(float4* addr, float4 v) {
    asm volatile("red.global.add.v4.f32 [%0], {%1, %2, %3, %4};"
                 :: "l"(addr), "f"(v.x), "f"(v.y), "f"(v.z), "f"(v.w)
                 : "memory");
}

__global__ void scatter_kernel(const int* __restrict__ ei_t,
                               const int* __restrict__ ei_i, int E) {
    int gid = blockIdx.x * blockDim.x + threadIdx.x;
    int halfT = E * 8;
    if (gid >= 2 * halfT) return;
    bool isT = gid < halfT;
    int g2 = isT ? gid : gid - halfT;
    int e = g2 >> 3;
    int j = g2 & 7;

    const int* ei = isT ? ei_t : ei_i;
    int s = __ldg(&ei[e]);
    int d = __ldg(&ei[E + e]);

    const float4* tab = isT ? g_ht : g_hi;
    float4* acc = isT ? g_A : g_B;

    float4 v = __ldg(&tab[s * 8 + j]);
    red_add_v4(&acc[d * 8 + j], v);
}

// ---------------------------------------------------------------------------
// finalize1: h1 = relu(A + B/max(cnt,1) + x @ Wr + br); zero A,B for block 2.
__global__ void finalize1_kernel(const float* __restrict__ x,
                                 const float* __restrict__ Wr,
                                 const float* __restrict__ br, int N) {
    __shared__ float sW[6 * 32];
    __shared__ float sb[32];
    for (int i = threadIdx.x; i < 6 * 32; i += blockDim.x) sW[i] = Wr[i];
    if (threadIdx.x < 32) sb[threadIdx.x] = br[threadIdx.x];
    __syncthreads();

    int t = blockIdx.x * blockDim.x + threadIdx.x;
    int n = t >> 3;
    int j = t & 7;
    int c = j * 4;
    if (n >= N) return;

    float inv = 1.0f / fmaxf(g_cnt[n], 1.0f);
    float4 a = g_A[n * 8 + j];
    float4 b = g_B[n * 8 + j];

    float4 r = make_float4(sb[c], sb[c + 1], sb[c + 2], sb[c + 3]);
#pragma unroll
    for (int k = 0; k < 6; k++) {
        float v = __ldg(&x[n * 6 + k]);
        r.x += v * sW[k * 32 + c];
        r.y += v * sW[k * 32 + c + 1];
        r.z += v * sW[k * 32 + c + 2];
        r.w += v * sW[k * 32 + c + 3];
    }
    float4 h;
    h.x = fmaxf(a.x + b.x * inv + r.x, 0.f);
    h.y = fmaxf(a.y + b.y * inv + r.y, 0.f);
    h.z = fmaxf(a.z + b.z * inv + r.z, 0.f);
    h.w = fmaxf(a.w + b.w * inv + r.w, 0.f);
    g_h1[n * 8 + j] = h;

    float4 z = make_float4(0.f, 0.f, 0.f, 0.f);
    g_A[n * 8 + j] = z;
    g_B[n * 8 + j] = z;
}

// ---------------------------------------------------------------------------
// finalize2 + classifier: h2 = relu(A + B/cnt + h1 @ Wr + br); out = h2 @ Wc + bc.
// One thread per node.
__global__ void finalize2_cls_kernel(const float* __restrict__ Wr,
                                     const float* __restrict__ br,
                                     const float* __restrict__ Wc,
                                     const float* __restrict__ bc,
                                     float* __restrict__ out, int N) {
    __shared__ float sWr[32 * 32];
    __shared__ float sbr[32];
    __shared__ float sWc[32 * 7];
    __shared__ float sbc[7];
    for (int i = threadIdx.x; i < 32 * 32; i += blockDim.x) sWr[i] = Wr[i];
    for (int i = threadIdx.x; i < 32 * 7; i += blockDim.x) sWc[i] = Wc[i];
    if (threadIdx.x < 32) sbr[threadIdx.x] = br[threadIdx.x];
    if (threadIdx.x < 7) sbc[threadIdx.x] = bc[threadIdx.x];
    __syncthreads();

    int n = blockIdx.x * blockDim.x + threadIdx.x;
    if (n >= N) return;

    float inv = 1.0f / fmaxf(g_cnt[n], 1.0f);

    // Load h1 row (32 floats).
    float h1r[32];
#pragma unroll
    for (int j = 0; j < 8; j++) {
        float4 v = __ldg(&g_h1[n * 8 + j]);
        h1r[j * 4 + 0] = v.x;
        h1r[j * 4 + 1] = v.y;
        h1r[j * 4 + 2] = v.z;
        h1r[j * 4 + 3] = v.w;
    }

    // Residual: h1 @ Wr + br.
    float res[32];
#pragma unroll
    for (int cc = 0; cc < 32; cc++) res[cc] = sbr[cc];
#pragma unroll
    for (int k = 0; k < 32; k++) {
        float v = h1r[k];
#pragma unroll
        for (int cc = 0; cc < 32; cc++) res[cc] += v * sWr[k * 32 + cc];
    }

    // relu + classifier accumulation.
    float acc[7];
#pragma unroll
    for (int m = 0; m < 7; m++) acc[m] = sbc[m];
#pragma unroll
    for (int j = 0; j < 8; j++) {
        float4 a = g_A[n * 8 + j];
        float4 b = g_B[n * 8 + j];
        float av[4] = {a.x, a.y, a.z, a.w};
        float bv[4] = {b.x, b.y, b.z, b.w};
#pragma unroll
        for (int l = 0; l < 4; l++) {
            int cc = j * 4 + l;
            float hv = fmaxf(av[l] + bv[l] * inv + res[cc], 0.f);
#pragma unroll
            for (int m = 0; m < 7; m++) acc[m] += hv * sWc[cc * 7 + m];
        }
    }
#pragma unroll
    for (int m = 0; m < 7; m++) out[n * 7 + m] = acc[m];
}

// ---------------------------------------------------------------------------
extern "C" void kernel_launch(void* const* d_in, const int* in_sizes, int n_in,
                              void* d_out, int out_size) {
    const float* x    = (const float*)d_in[0];
    const int*   ei_t = (const int*)d_in[1];
    const int*   ei_i = (const int*)d_in[2];
    const float* W1t  = (const float*)d_in[3];
    const float* b1t  = (const float*)d_in[4];
    const float* W1i  = (const float*)d_in[5];
    const float* b1i  = (const float*)d_in[6];
    const float* W1r  = (const float*)d_in[7];
    const float* b1r  = (const float*)d_in[8];
    const float* W2t  = (const float*)d_in[9];
    const float* b2t  = (const float*)d_in[10];
    const float* W2i  = (const float*)d_in[11];
    const float* b2i  = (const float*)d_in[12];
    const float* W2r  = (const float*)d_in[13];
    const float* b2r  = (const float*)d_in[14];
    const float* Wc   = (const float*)d_in[15];
    const float* bc   = (const float*)d_in[16];
    float* out = (float*)d_out;

    int N = in_sizes[0] / 6;
    int E = in_sizes[1] / 2;

    const int TB = 256;
    int zero_items = 2 * N * 8 + N;
    int scat_items = 2 * E * 8;

    // Prologue: clear accumulators + counts, compute inter in-degrees.
    zero_kernel<<<(zero_items + TB - 1) / TB, TB>>>(N);
    count_kernel<<<(E + TB - 1) / TB, TB>>>(ei_i, E);

    // Block 1.
    transform_kernel<6><<<(N * 8 + TB - 1) / TB, TB>>>(x, W1t, b1t, W1i, b1i, N);
    scatter_kernel<<<(scat_items + TB - 1) / TB, TB>>>(ei_t, ei_i, E);
    finalize1_kernel<<<(N * 8 + TB - 1) / TB, TB>>>(x, W1r, b1r, N);

    // Block 2 (A/B were re-zeroed by finalize1).
    transform_kernel<32><<<(N * 8 + TB - 1) / TB, TB>>>(nullptr, W2t, b2t, W2i, b2i, N);
    scatter_kernel<<<(scat_items + TB - 1) / TB, TB>>>(ei_t, ei_i, E);

    // Finalize block 2 fused with classifier.
    finalize2_cls_kernel<<<(N + TB - 1) / TB, TB>>>(W2r, b2r, Wc, bc, out, N);
}

// round 4
// speedup vs baseline: 1.3665x; 1.3665x over previous
#include <cuda_runtime.h>

#define N_MAX 100000
#define E_MAX 2000000

// Scratch (allocation-free). Referenced ONLY from device code.
__device__ float4 g_ht[N_MAX * 8];     // transformed table (Wt path)
__device__ float4 g_hi[N_MAX * 8];     // transformed table (Wi path)
__device__ float4 g_h1[N_MAX * 8];     // block-1 output
__device__ float4 g_h2[N_MAX * 8];     // block-2 output
__device__ int    g_deg_t[N_MAX];
__device__ int    g_deg_i[N_MAX];
__device__ int    g_off_t[N_MAX];      // CSR segment start (unordered partition)
__device__ int    g_off_i[N_MAX];
__device__ int    g_cur_t[N_MAX];      // fill cursors
__device__ int    g_cur_i[N_MAX];
__device__ int    g_srcs_t[E_MAX];     // CSR source indices grouped by dst
__device__ int    g_srcs_i[E_MAX];
__device__ int    g_ctr[2];            // segment allocators

// ---------------------------------------------------------------------------
__global__ void init_kernel(int N) {
    int i = blockIdx.x * blockDim.x + threadIdx.x;
    if (i < N) { g_deg_t[i] = 0; g_deg_i[i] = 0; }
    if (i < 2) g_ctr[i] = 0;
}

__global__ void hist_kernel(const int* __restrict__ ei_t,
                            const int* __restrict__ ei_i, int E) {
    int e = blockIdx.x * blockDim.x + threadIdx.x;
    if (e < E) {
        atomicAdd(&g_deg_t[__ldg(&ei_t[E + e])], 1);
    } else if (e < 2 * E) {
        atomicAdd(&g_deg_i[__ldg(&ei_i[E + (e - E)])], 1);
    }
}

// Warp-aggregated segment allocation: disjoint contiguous segments per node,
// order irrelevant (no global prefix scan needed).
__global__ void alloc_kernel(int N) {
    int i = blockIdx.x * blockDim.x + threadIdx.x;
    int lane = threadIdx.x & 31;

    int dt = 0, di = 0;
    if (i < N) { dt = g_deg_t[i]; di = g_deg_i[i]; }

    // warp inclusive scan
    int st = dt, si = di;
#pragma unroll
    for (int ofs = 1; ofs < 32; ofs <<= 1) {
        int at_ = __shfl_up_sync(0xffffffffu, st, ofs);
        int ai_ = __shfl_up_sync(0xffffffffu, si, ofs);
        if (lane >= ofs) { st += at_; si += ai_; }
    }

    int baset = 0, basei = 0;
    if (lane == 31) {
        baset = atomicAdd(&g_ctr[0], st);
        basei = atomicAdd(&g_ctr[1], si);
    }
    baset = __shfl_sync(0xffffffffu, baset, 31);
    basei = __shfl_sync(0xffffffffu, basei, 31);

    if (i < N) {
        int ot = baset + st - dt;   // exclusive within warp + warp base
        int oi = basei + si - di;
        g_off_t[i] = ot;  g_cur_t[i] = ot;
        g_off_i[i] = oi;  g_cur_i[i] = oi;
    }
}

__global__ void fill_kernel(const int* __restrict__ ei_t,
                            const int* __restrict__ ei_i, int E) {
    int e = blockIdx.x * blockDim.x + threadIdx.x;
    if (e < E) {
        int s = __ldg(&ei_t[e]);
        int d = __ldg(&ei_t[E + e]);
        int pos = atomicAdd(&g_cur_t[d], 1);
        g_srcs_t[pos] = s;
    } else if (e < 2 * E) {
        int e2 = e - E;
        int s = __ldg(&ei_i[e2]);
        int d = __ldg(&ei_i[E + e2]);
        int pos = atomicAdd(&g_cur_i[d], 1);
        g_srcs_i[pos] = s;
    }
}

// ---------------------------------------------------------------------------
// Transform: ht = in @ Wt + bt ; hi = in @ Wi + bi. One thread per (node, j).
// PHASE 1 reads x (kernel param, K=6); PHASE 2 reads g_h1 (device symbol, K=32).
template <int K, int PHASE>
__global__ void transform_kernel(const float* __restrict__ in,
                                 const float* __restrict__ Wt,
                                 const float* __restrict__ bt,
                                 const float* __restrict__ Wi,
                                 const float* __restrict__ bi, int N) {
    __shared__ float sWt[K * 32];
    __shared__ float sWi[K * 32];
    __shared__ float sbt[32];
    __shared__ float sbi[32];
    for (int i = threadIdx.x; i < K * 32; i += blockDim.x) {
        sWt[i] = Wt[i];
        sWi[i] = Wi[i];
    }
    if (threadIdx.x < 32) {
        sbt[threadIdx.x] = bt[threadIdx.x];
        sbi[threadIdx.x] = bi[threadIdx.x];
    }
    __syncthreads();

    int t = blockIdx.x * blockDim.x + threadIdx.x;
    int n = t >> 3;
    int j = t & 7;
    int c = j * 4;
    if (n >= N) return;

    const float* src = (PHASE == 2) ? (const float*)g_h1 : in;  // device-side

    float4 at = make_float4(sbt[c], sbt[c + 1], sbt[c + 2], sbt[c + 3]);
    float4 ai = make_float4(sbi[c], sbi[c + 1], sbi[c + 2], sbi[c + 3]);
#pragma unroll
    for (int k = 0; k < K; k++) {
        float v = __ldg(&src[n * K + k]);
        at.x += v * sWt[k * 32 + c];
        at.y += v * sWt[k * 32 + c + 1];
        at.z += v * sWt[k * 32 + c + 2];
        at.w += v * sWt[k * 32 + c + 3];
        ai.x += v * sWi[k * 32 + c];
        ai.y += v * sWi[k * 32 + c + 1];
        ai.z += v * sWi[k * 32 + c + 2];
        ai.w += v * sWi[k * 32 + c + 3];
    }
    g_ht[n * 8 + j] = at;
    g_hi[n * 8 + j] = ai;
}

// ---------------------------------------------------------------------------
// Gather-aggregate over a CSR segment with software-pipelined MLP=4.
__device__ __forceinline__ float4 seg_gather(const int* __restrict__ srcs,
                                             const float4* __restrict__ tab,
                                             int beg, int end, int j) {
    float4 acc = make_float4(0.f, 0.f, 0.f, 0.f);
    int e = beg;
    for (; e + 4 <= end; e += 4) {
        int s0 = __ldg(&srcs[e]);
        int s1 = __ldg(&srcs[e + 1]);
        int s2 = __ldg(&srcs[e + 2]);
        int s3 = __ldg(&srcs[e + 3]);
        float4 v0 = __ldg(&tab[s0 * 8 + j]);
        float4 v1 = __ldg(&tab[s1 * 8 + j]);
        float4 v2 = __ldg(&tab[s2 * 8 + j]);
        float4 v3 = __ldg(&tab[s3 * 8 + j]);
        acc.x += v0.x + v1.x + v2.x + v3.x;
        acc.y += v0.y + v1.y + v2.y + v3.y;
        acc.z += v0.z + v1.z + v2.z + v3.z;
        acc.w += v0.w + v1.w + v2.w + v3.w;
    }
    for (; e < end; e++) {
        int s = __ldg(&srcs[e]);
        float4 v = __ldg(&tab[s * 8 + j]);
        acc.x += v.x; acc.y += v.y; acc.z += v.z; acc.w += v.w;
    }
    return acc;
}

// Fused block: h = relu(agg_t + agg_i/max(cnt,1) + xin @ Wr + br).
// PHASE 1: xin = x (param), writes g_h1. PHASE 2: xin = g_h1, writes g_h2.
template <int K, int PHASE>
__global__ void block_kernel(const float* __restrict__ xin_param,
                             const float* __restrict__ Wr,
                             const float* __restrict__ br, int N) {
    __shared__ float sWr[K * 32];
    __shared__ float sbr[32];
    for (int i = threadIdx.x; i < K * 32; i += blockDim.x) sWr[i] = Wr[i];
    if (threadIdx.x < 32) sbr[threadIdx.x] = br[threadIdx.x];
    __syncthreads();

    int t = blockIdx.x * blockDim.x + threadIdx.x;
    int n = t >> 3;
    int j = t & 7;
    int c = j * 4;
    if (n >= N) return;

    const float* xin = (PHASE == 2) ? (const float*)g_h1 : xin_param;

    // Residual
    float4 r = make_float4(sbr[c], sbr[c + 1], sbr[c + 2], sbr[c + 3]);
#pragma unroll
    for (int k = 0; k < K; k++) {
        float v = __ldg(&xin[n * K + k]);
        r.x += v * sWr[k * 32 + c];
        r.y += v * sWr[k * 32 + c + 1];
        r.z += v * sWr[k * 32 + c + 2];
        r.w += v * sWr[k * 32 + c + 3];
    }

    // temp (sum) aggregation
    int bt_ = g_off_t[n];
    int dt_ = g_deg_t[n];
    float4 at = seg_gather(g_srcs_t, g_ht, bt_, bt_ + dt_, j);

    // inter (mean) aggregation
    int bi_ = g_off_i[n];
    int di_ = g_deg_i[n];
    float4 ai = seg_gather(g_srcs_i, g_hi, bi_, bi_ + di_, j);
    float inv = 1.0f / fmaxf((float)di_, 1.0f);

    float4 h;
    h.x = fmaxf(at.x + ai.x * inv + r.x, 0.f);
    h.y = fmaxf(at.y + ai.y * inv + r.y, 0.f);
    h.z = fmaxf(at.z + ai.z * inv + r.z, 0.f);
    h.w = fmaxf(at.w + ai.w * inv + r.w, 0.f);

    if (PHASE == 2) g_h2[n * 8 + j] = h;
    else            g_h1[n * 8 + j] = h;
}

// ---------------------------------------------------------------------------
// Classifier: out = g_h2 @ Wc + bc. One thread per node.
__global__ void cls_kernel(const float* __restrict__ Wc,
                           const float* __restrict__ bc,
                           float* __restrict__ out, int N) {
    __shared__ float sWc[32 * 7];
    __shared__ float sbc[7];
    for (int i = threadIdx.x; i < 32 * 7; i += blockDim.x) sWc[i] = Wc[i];
    if (threadIdx.x < 7) sbc[threadIdx.x] = bc[threadIdx.x];
    __syncthreads();

    int n = blockIdx.x * blockDim.x + threadIdx.x;
    if (n >= N) return;

    float acc[7];
#pragma unroll
    for (int m = 0; m < 7; m++) acc[m] = sbc[m];
#pragma unroll
    for (int jj = 0; jj < 8; jj++) {
        float4 v = g_h2[n * 8 + jj];
        float hv[4] = {v.x, v.y, v.z, v.w};
#pragma unroll
        for (int l = 0; l < 4; l++) {
            int k = jj * 4 + l;
#pragma unroll
            for (int m = 0; m < 7; m++) acc[m] += hv[l] * sWc[k * 7 + m];
        }
    }
#pragma unroll
    for (int m = 0; m < 7; m++) out[n * 7 + m] = acc[m];
}

// ---------------------------------------------------------------------------
extern "C" void kernel_launch(void* const* d_in, const int* in_sizes, int n_in,
                              void* d_out, int out_size) {
    const float* x    = (const float*)d_in[0];
    const int*   ei_t = (const int*)d_in[1];
    const int*   ei_i = (const int*)d_in[2];
    const float* W1t  = (const float*)d_in[3];
    const float* b1t  = (const float*)d_in[4];
    const float* W1i  = (const float*)d_in[5];
    const float* b1i  = (const float*)d_in[6];
    const float* W1r  = (const float*)d_in[7];
    const float* b1r  = (const float*)d_in[8];
    const float* W2t  = (const float*)d_in[9];
    const float* b2t  = (const float*)d_in[10];
    const float* W2i  = (const float*)d_in[11];
    const float* b2i  = (const float*)d_in[12];
    const float* W2r  = (const float*)d_in[13];
    const float* b2r  = (const float*)d_in[14];
    const float* Wc   = (const float*)d_in[15];
    const float* bc   = (const float*)d_in[16];
    float* out = (float*)d_out;

    int N = in_sizes[0] / 6;
    int E = in_sizes[1] / 2;

    const int TB = 256;

    // --- CSR build (both edge types) ---
    init_kernel<<<(N + TB - 1) / TB, TB>>>(N);
    hist_kernel<<<(2 * E + TB - 1) / TB, TB>>>(ei_t, ei_i, E);
    alloc_kernel<<<(N + TB - 1) / TB, TB>>>(N);
    fill_kernel<<<(2 * E + TB - 1) / TB, TB>>>(ei_t, ei_i, E);

    // --- Block 1 ---
    transform_kernel<6, 1><<<(N * 8 + TB - 1) / TB, TB>>>(x, W1t, b1t, W1i, b1i, N);
    block_kernel<6, 1><<<(N * 8 + TB - 1) / TB, TB>>>(x, W1r, b1r, N);

    // --- Block 2 ---
    transform_kernel<32, 2><<<(N * 8 + TB - 1) / TB, TB>>>(nullptr, W2t, b2t, W2i, b2i, N);
    block_kernel<32, 2><<<(N * 8 + TB - 1) / TB, TB>>>(nullptr, W2r, b2r, N);

    // --- Classifier ---
    cls_kernel<<<(N + TB - 1) / TB, TB>>>(Wc, bc, out, N);
}